// round 9
// baseline (speedup 1.0000x reference)
#include <cuda_runtime.h>
#include <cuda_fp16.h>
#include <cstdint>
#include <math.h>

typedef __half fp16;

#define BB  16
#define CC  512
#define HW  1024
#define GG  32
#define CPG 16
#define EPSV 1e-5f

// ---------------------------------------------------------------------------
// Scratch: pure fp16 tensors (single plane each) + fp32 scores.
// ---------------------------------------------------------------------------
#define PL_W    ((size_t)2048*512)          // Wq|Wk|Wv|Wo rows x 512
#define PL_GN   ((size_t)BB*HW*512)
#define PL_Q    ((size_t)BB*HW*512)
#define PL_K    ((size_t)BB*HW*512)
#define PL_V    ((size_t)BB*CC*HW)          // [b][c][i]
#define PL_ATT  ((size_t)BB*HW*HW)          // [b][i][j]
#define PL_HH   ((size_t)BB*HW*512)         // [b][i][c]

#define OFF_WH   ((size_t)0)
#define OFF_GNH  (OFF_WH  + PL_W*2)
#define OFF_QH   (OFF_GNH + PL_GN*2)
#define OFF_KH   (OFF_QH  + PL_Q*2)
#define OFF_VH   (OFF_KH  + PL_K*2)
#define OFF_AH   (OFF_VH  + PL_V*2)
#define OFF_HHH  (OFF_AH  + PL_ATT*2)
#define OFF_S    (OFF_HHH + PL_HH*2)
#define SZ_S     ((size_t)BB*HW*HW*4)
#define SCRATCH_BYTES (OFF_S + SZ_S)

__device__ __align__(256) unsigned char g_scratch[SCRATCH_BYTES];

// ---------------------------------------------------------------------------
// PTX helpers
// ---------------------------------------------------------------------------
__device__ __forceinline__ uint32_t smem_u32(const void* p) {
    uint32_t a;
    asm("{ .reg .u64 t; cvta.to.shared.u64 t, %1; cvt.u32.u64 %0, t; }" : "=r"(a) : "l"(p));
    return a;
}
__device__ __forceinline__ void ldsm4(uint32_t* r, uint32_t addr) {
    asm volatile("ldmatrix.sync.aligned.m8n8.x4.shared.b16 {%0,%1,%2,%3}, [%4];"
                 : "=r"(r[0]), "=r"(r[1]), "=r"(r[2]), "=r"(r[3]) : "r"(addr));
}
__device__ __forceinline__ void mma16816(float* d, const uint32_t* a, const uint32_t* b) {
    asm volatile("mma.sync.aligned.m16n8k16.row.col.f32.f16.f16.f32 "
        "{%0,%1,%2,%3}, {%4,%5,%6,%7}, {%8,%9}, {%0,%1,%2,%3};"
        : "+f"(d[0]), "+f"(d[1]), "+f"(d[2]), "+f"(d[3])
        : "r"(a[0]), "r"(a[1]), "r"(a[2]), "r"(a[3]), "r"(b[0]), "r"(b[1]));
}
__device__ __forceinline__ void cpasync16(uint32_t dst, const void* src) {
    asm volatile("cp.async.cg.shared.global [%0], [%1], 16;" :: "r"(dst), "l"(src));
}
#define CP_COMMIT() asm volatile("cp.async.commit_group;" ::: "memory")
#define CP_WAIT1()  asm volatile("cp.async.wait_group 1;" ::: "memory")
#define CP_WAIT0()  asm volatile("cp.async.wait_group 0;" ::: "memory")

__device__ __forceinline__ void storeH2(fp16* ph, float v0, float v1) {
    *(half2*)ph = __halves2half2(__float2half(v0), __float2half(v1));
}

// ---------------------------------------------------------------------------
// Weight conversion: rows 0-511 Wq, 512-1023 Wk, 1024-1535 Wv, 1536-2047 Wo
// ---------------------------------------------------------------------------
__global__ __launch_bounds__(256) void convert_w_kernel(
    const float* __restrict__ Wq, const float* __restrict__ Wk,
    const float* __restrict__ Wv, const float* __restrict__ Wo,
    fp16* __restrict__ WH)
{
    int r = blockIdx.x;
    int tid = threadIdx.x;
    const float* src = (r < 512)  ? Wq + (size_t)r * 512
                     : (r < 1024) ? Wk + (size_t)(r-512) * 512
                     : (r < 1536) ? Wv + (size_t)(r-1024) * 512
                                  : Wo + (size_t)(r-1536) * 512;
    fp16* dh = WH + (size_t)r * 512;
    for (int k = tid; k < 512; k += 256) dh[k] = __float2half(src[k]);
}

// ---------------------------------------------------------------------------
// GroupNorm + SiLU -> gn plane [b][n][512]
// ---------------------------------------------------------------------------
__global__ __launch_bounds__(256) void gn_silu_kernel(
    const float* __restrict__ x, const float* __restrict__ gamma,
    const float* __restrict__ beta, fp16* __restrict__ gnH)
{
    int bg = blockIdx.x;
    int b = bg / GG, g = bg % GG;
    const float* xp = x + ((size_t)b*CC + g*CPG) * HW;
    int tid = threadIdx.x;

    float s = 0.f, ss = 0.f;
    for (int i = tid; i < CPG*HW; i += 256) {
        float v = xp[i];
        s += v; ss += v*v;
    }
    __shared__ float sh0[256], sh1[256];
    sh0[tid] = s; sh1[tid] = ss;
    __syncthreads();
    for (int o = 128; o > 0; o >>= 1) {
        if (tid < o) { sh0[tid] += sh0[tid+o]; sh1[tid] += sh1[tid+o]; }
        __syncthreads();
    }
    const float inv_n = 1.f / (float)(CPG*HW);
    float mean = sh0[0] * inv_n;
    float var  = sh1[0] * inv_n - mean*mean;
    float rstd = rsqrtf(var + EPSV);

    float gm[CPG], bt[CPG];
    #pragma unroll
    for (int cl = 0; cl < CPG; cl++) { gm[cl] = gamma[g*CPG+cl]; bt[cl] = beta[g*CPG+cl]; }

    for (int n = tid; n < HW; n += 256) {
        fp16* dh = gnH + ((size_t)b*HW + n) * 512 + g*CPG;
        #pragma unroll
        for (int cl = 0; cl < CPG; cl += 2) {
            float v0 = (xp[cl*HW + n]     - mean) * rstd * gm[cl]   + bt[cl];
            float v1 = (xp[(cl+1)*HW + n] - mean) * rstd * gm[cl+1] + bt[cl+1];
            v0 = v0 / (1.f + __expf(-v0));
            v1 = v1 / (1.f + __expf(-v1));
            storeH2(dh + cl, v0, v1);
        }
    }
}

// ---------------------------------------------------------------------------
// Row softmax -> attn plane [b*i][1024]
// ---------------------------------------------------------------------------
__global__ __launch_bounds__(256) void softmax_kernel(
    const float* __restrict__ s, fp16* __restrict__ aH)
{
    const float* sp = s + (size_t)blockIdx.x * HW;
    size_t ro = (size_t)blockIdx.x * HW;
    int tid = threadIdx.x;
    float4 v = *(const float4*)(sp + tid*4);
    float m = fmaxf(fmaxf(v.x, v.y), fmaxf(v.z, v.w));

    __shared__ float sh[256];
    sh[tid] = m; __syncthreads();
    for (int o = 128; o > 0; o >>= 1) {
        if (tid < o) sh[tid] = fmaxf(sh[tid], sh[tid+o]);
        __syncthreads();
    }
    m = sh[0];
    __syncthreads();

    v.x = __expf(v.x - m); v.y = __expf(v.y - m);
    v.z = __expf(v.z - m); v.w = __expf(v.w - m);
    sh[tid] = v.x + v.y + v.z + v.w; __syncthreads();
    for (int o = 128; o > 0; o >>= 1) {
        if (tid < o) sh[tid] += sh[tid+o];
        __syncthreads();
    }
    float inv = 1.f / sh[0];
    storeH2(aH + ro + tid*4,     v.x*inv, v.y*inv);
    storeH2(aH + ro + tid*4 + 2, v.z*inv, v.w*inv);
}

// ---------------------------------------------------------------------------
// HMMA GEMM, pure fp16. CTA tile 128x128, 4 warps (2x2), warp tile 64x64,
// K-chunk 64, 3-stage cp.async pipeline, XOR-swizzled smem, and
// FRAGMENT DOUBLE-BUFFERING: ldsm for k16-step t+1 issued before MMAs of t.
// EPI: 0=QK  1=V  2=SCORES  3=AV  4=OUT
// ---------------------------------------------------------------------------
#define KC       64
#define OPB      16384                 // 128 rows * 128 B
#define STAGE_B  (2*OPB)               // 32 KB
#define SMEM_BYTES (3*STAGE_B)         // 96 KB

__device__ __forceinline__ void load_stage(uint32_t dst, const fp16* Ap, const fp16* Bp,
                                           int Kb, int tid)
{
    #pragma unroll
    for (int it = 0; it < 8; it++) {
        int e   = it*128 + tid;        // 0..1023
        int row = e >> 3, grp = e & 7;
        uint32_t off = (uint32_t)(row*128 + ((grp ^ (row & 7)) << 4));
        cpasync16(dst + off,       Ap + (size_t)row * Kb + grp*8);
        cpasync16(dst + OPB + off, Bp + (size_t)row * Kb + grp*8);
    }
}

template<int EPI>
__global__ __launch_bounds__(128, 2) void hmma_gemm(
    const fp16* __restrict__ AH, size_t aStr,
    const fp16* __restrict__ BH, size_t bStr, int Kb,
    const float* __restrict__ bias, const float* __restrict__ bias2,
    const float* __restrict__ xres,
    float* __restrict__ fOut, fp16* __restrict__ oH, fp16* __restrict__ o2H,
    float scale)
{
    extern __shared__ char smem[];
    const uint32_t sbase = smem_u32(smem);
    const int tid  = threadIdx.x;
    const int lane = tid & 31, wid = tid >> 5;
    const int wm = wid >> 1, wn = wid & 1;
    const int bz = blockIdx.z;
    const int m0 = blockIdx.y * 128, n0 = blockIdx.x * 128;

    const fp16* AHb = AH + bz*aStr + (size_t)m0 * Kb;
    const fp16* BHb = BH + bz*bStr + (size_t)n0 * Kb;

    const int nch = Kb >> 6;

    // ldmatrix per-thread geometry
    const int aR0 = wm*64 + (lane & 15);
    const int aGs = lane >> 4;
    const int bR0 = wn*64 + (lane & 7) + ((lane >> 4) & 1) * 8;
    const int bGs = (lane >> 3) & 1;

    float acc[4][8][4];
    #pragma unroll
    for (int i = 0; i < 4; i++)
        #pragma unroll
        for (int j = 0; j < 8; j++)
            #pragma unroll
            for (int c = 0; c < 4; c++) acc[i][j][c] = 0.f;

    // fragment ping-pong buffers
    uint32_t afr[2][4][4];
    uint32_t bfr[2][8][2];

    // prologue: chunks 0,1
    load_stage(sbase,           AHb,      BHb,      Kb, tid);  CP_COMMIT();
    load_stage(sbase + STAGE_B, AHb + KC, BHb + KC, Kb, tid);  CP_COMMIT();

    int stage = 0;
    for (int t = 0; t < nch; t++) {
        if (t + 2 < nch) CP_WAIT1(); else CP_WAIT0();
        __syncthreads();

        const uint32_t abase = sbase + stage*STAGE_B;
        const uint32_t bbase = abase + OPB;

        // issue step-0 fragment loads FIRST (hide ldsm latency behind cp.async issue)
        {
            uint32_t gA = (uint32_t)aGs;
            uint32_t gB = (uint32_t)bGs;
            #pragma unroll
            for (int mf = 0; mf < 4; mf++) {
                int r = aR0 + mf*16;
                ldsm4(afr[0][mf], abase + (uint32_t)(r*128) + ((gA ^ (uint32_t)(r & 7)) << 4));
            }
            #pragma unroll
            for (int p = 0; p < 4; p++) {
                int r = bR0 + p*16;
                uint32_t rr[4];
                ldsm4(rr, bbase + (uint32_t)(r*128) + ((gB ^ (uint32_t)(r & 7)) << 4));
                bfr[0][2*p][0]   = rr[0]; bfr[0][2*p][1]   = rr[1];
                bfr[0][2*p+1][0] = rr[2]; bfr[0][2*p+1][1] = rr[3];
            }
        }

        if (t + 2 < nch) {
            int kk = (t + 2) * KC;
            int s2 = stage + 2; if (s2 >= 3) s2 -= 3;
            load_stage(sbase + s2*STAGE_B, AHb + kk, BHb + kk, Kb, tid);
            CP_COMMIT();
        }

        // 4 k16 steps with fragment double buffering
        #pragma unroll
        for (int step = 0; step < 4; step++) {
            int cur = step & 1, nxt = cur ^ 1;
            if (step < 3) {
                uint32_t gA = (uint32_t)((step+1)*2 + aGs);
                uint32_t gB = (uint32_t)((step+1)*2 + bGs);
                #pragma unroll
                for (int mf = 0; mf < 4; mf++) {
                    int r = aR0 + mf*16;
                    ldsm4(afr[nxt][mf], abase + (uint32_t)(r*128) + ((gA ^ (uint32_t)(r & 7)) << 4));
                }
                #pragma unroll
                for (int p = 0; p < 4; p++) {
                    int r = bR0 + p*16;
                    uint32_t rr[4];
                    ldsm4(rr, bbase + (uint32_t)(r*128) + ((gB ^ (uint32_t)(r & 7)) << 4));
                    bfr[nxt][2*p][0]   = rr[0]; bfr[nxt][2*p][1]   = rr[1];
                    bfr[nxt][2*p+1][0] = rr[2]; bfr[nxt][2*p+1][1] = rr[3];
                }
            }
            #pragma unroll
            for (int mf = 0; mf < 4; mf++)
                #pragma unroll
                for (int nf = 0; nf < 8; nf++)
                    mma16816(acc[mf][nf], afr[cur][mf], bfr[cur][nf]);
        }

        stage++; if (stage == 3) stage = 0;
    }

    // ---------------- epilogue ----------------
    const int tr = lane >> 2;
    const int tc = (lane & 3) * 2;

    #pragma unroll
    for (int mf = 0; mf < 4; mf++) {
        #pragma unroll
        for (int half = 0; half < 2; half++) {
            int r = m0 + wm*64 + mf*16 + tr + half*8;
            #pragma unroll
            for (int nf = 0; nf < 8; nf++) {
                int c = n0 + wn*64 + nf*8 + tc;
                float d0 = acc[mf][nf][half*2 + 0];
                float d1 = acc[mf][nf][half*2 + 1];

                if (EPI == 0) {                 // QK: D[i][ch], ch<512 q else k
                    if (c < 512) {
                        d0 += bias[c]; d1 += bias[c+1];
                        size_t idx = ((size_t)bz*HW + r) * 512 + c;
                        storeH2(oH + idx, d0, d1);
                    } else {
                        d0 += bias2[c-512]; d1 += bias2[c-511];
                        size_t idx = ((size_t)bz*HW + r) * 512 + (c - 512);
                        storeH2(o2H + idx, d0, d1);
                    }
                } else if (EPI == 1) {          // V: D[ch][i]
                    float bb = bias[r];
                    size_t idx = ((size_t)bz*CC + r) * HW + c;
                    storeH2(oH + idx, d0+bb, d1+bb);
                } else if (EPI == 2) {          // scores fp32 * scale
                    *(float2*)(fOut + ((size_t)bz*HW + r) * HW + c)
                        = make_float2(d0*scale, d1*scale);
                } else if (EPI == 3) {          // AV: D[i][ch]
                    size_t idx = ((size_t)bz*HW + r) * 512 + c;
                    storeH2(oH + idx, d0, d1);
                } else {                        // OUT: + bias + residual
                    float bb = bias[r];
                    size_t off = ((size_t)bz*CC + r) * HW + c;
                    float2 xr = *(const float2*)(xres + off);
                    *(float2*)(fOut + off) = make_float2(d0+bb+xr.x, d1+bb+xr.y);
                }
            }
        }
    }
}

// ---------------------------------------------------------------------------
extern "C" void kernel_launch(void* const* d_in, const int* in_sizes, int n_in,
                              void* d_out, int out_size)
{
    const float* x     = (const float*)d_in[0];
    const float* Wq    = (const float*)d_in[1];
    const float* bq    = (const float*)d_in[2];
    const float* Wk    = (const float*)d_in[3];
    const float* bk    = (const float*)d_in[4];
    const float* Wv    = (const float*)d_in[5];
    const float* bv    = (const float*)d_in[6];
    const float* Wo    = (const float*)d_in[7];
    const float* bo    = (const float*)d_in[8];
    const float* gamma = (const float*)d_in[9];
    const float* beta  = (const float*)d_in[10];
    float* out = (float*)d_out;

    unsigned char* base = nullptr;
    cudaGetSymbolAddress((void**)&base, g_scratch);
    fp16*  WH  = (fp16*)(base + OFF_WH);
    fp16*  gnH = (fp16*)(base + OFF_GNH);
    fp16*  qH  = (fp16*)(base + OFF_QH);
    fp16*  kH  = (fp16*)(base + OFF_KH);
    fp16*  vH  = (fp16*)(base + OFF_VH);
    fp16*  aH  = (fp16*)(base + OFF_AH);
    fp16*  hhH = (fp16*)(base + OFF_HHH);
    float* sS  = (float*)(base + OFF_S);

    cudaFuncSetAttribute(hmma_gemm<0>, cudaFuncAttributeMaxDynamicSharedMemorySize, SMEM_BYTES);
    cudaFuncSetAttribute(hmma_gemm<1>, cudaFuncAttributeMaxDynamicSharedMemorySize, SMEM_BYTES);
    cudaFuncSetAttribute(hmma_gemm<2>, cudaFuncAttributeMaxDynamicSharedMemorySize, SMEM_BYTES);
    cudaFuncSetAttribute(hmma_gemm<3>, cudaFuncAttributeMaxDynamicSharedMemorySize, SMEM_BYTES);
    cudaFuncSetAttribute(hmma_gemm<4>, cudaFuncAttributeMaxDynamicSharedMemorySize, SMEM_BYTES);

    const float scale = 1.0f / sqrtf((float)CC);

    convert_w_kernel<<<2048, 256>>>(Wq, Wk, Wv, Wo, WH);
    gn_silu_kernel<<<BB*GG, 256>>>(x, gamma, beta, gnH);

    const size_t PXS = (size_t)HW * 512;   // pixel-row plane stride (per b)
    const size_t CHS = (size_t)CC * HW;    // channel-row plane stride (per b)

    // QK: M=1024 pixels (A=gn), N=1024 q|k rows (B=W), K=512
    hmma_gemm<0><<<dim3(8, 8, BB), 128, SMEM_BYTES>>>(
        gnH, PXS, WH, 0, 512, bq, bk, nullptr, nullptr, qH, kH, 0.f);

    // V: M=512 channels (A=Wv), N=1024 pixels (B=gn), K=512
    hmma_gemm<1><<<dim3(8, 4, BB), 128, SMEM_BYTES>>>(
        WH + (size_t)1024*512, 0, gnH, PXS, 512,
        bv, nullptr, nullptr, nullptr, vH, nullptr, 0.f);

    // scores: M=1024 i (A=q), N=1024 j (B=k), K=512 -> fp32 * scale
    hmma_gemm<2><<<dim3(8, 8, BB), 128, SMEM_BYTES>>>(
        qH, PXS, kH, PXS, 512, nullptr, nullptr, nullptr,
        sS, nullptr, nullptr, scale);

    softmax_kernel<<<BB*HW, 256>>>(sS, aH);

    // AV: M=1024 i (A=attn), N=512 ch (B=v), K=1024 -> hh
    hmma_gemm<3><<<dim3(4, 8, BB), 128, SMEM_BYTES>>>(
        aH, (size_t)HW*HW, vH, CHS, 1024, nullptr, nullptr, nullptr,
        nullptr, hhH, nullptr, 0.f);

    // OUT: M=512 ch (A=Wo), N=1024 i (B=hh), K=512, +bo +x
    hmma_gemm<4><<<dim3(8, 4, BB), 128, SMEM_BYTES>>>(
        WH + (size_t)1536*512, 0, hhH, PXS, 512,
        bo, nullptr, x, out, nullptr, nullptr, 0.f);
}